// round 2
// baseline (speedup 1.0000x reference)
#include <cuda_runtime.h>

#define NN   100000
#define EE   1000000
#define INC  128
#define HID  32
#define NH1  8
#define OUTC 40
#define NEGS 0.2f

// ---------------- device scratch (no dynamic allocation allowed) ----------------
__device__ __align__(16) float g_h1[(size_t)NN * 256];   // layer1 per-head features [N,8,32]
__device__ __align__(16) float g_x2[(size_t)NN * 256];   // relu(layer1 out)
__device__ __align__(16) float g_as1[NN * NH1];
__device__ __align__(16) float g_ad1[NN * NH1];
__device__ __align__(16) float g_h2[NN * HID];
__device__ __align__(16) float g_as2[NN];
__device__ __align__(16) float g_ad2[NN];
__device__ __align__(16) float g_o2[NN * HID];
__device__ int   g_cnt[NN];
__device__ int   g_rowptr[NN + 1];
__device__ int   g_cursor[NN];
__device__ int   g_col[EE];

// ---------------- CSR build ----------------
__global__ void k_zero() {
    int i = blockIdx.x * blockDim.x + threadIdx.x;
    if (i < NN) g_cnt[i] = 0;
}

// edge_index is int32 (JAX silently downcasts int64 -> int32 without x64 mode)
__global__ void k_hist(const int* __restrict__ ei) {
    int e = blockIdx.x * blockDim.x + threadIdx.x;
    if (e < EE) {
        int d = ei[EE + e];
        atomicAdd(&g_cnt[d], 1);
    }
}

// single-block scan over 100K ints (exclusive prefix -> rowptr, cursor)
__global__ void k_scan() {
    __shared__ int ws[32];
    int tid = threadIdx.x;
    int lane = tid & 31, wid = tid >> 5;
    int carry = 0;
    for (int base = 0; base < NN; base += 1024) {
        int i = base + tid;
        int v = (i < NN) ? g_cnt[i] : 0;
        int x = v;
        #pragma unroll
        for (int o = 1; o < 32; o <<= 1) {
            int y = __shfl_up_sync(0xffffffffu, x, o);
            if (lane >= o) x += y;
        }
        if (lane == 31) ws[wid] = x;
        __syncthreads();
        if (wid == 0) {
            int s = ws[lane];
            #pragma unroll
            for (int o = 1; o < 32; o <<= 1) {
                int y = __shfl_up_sync(0xffffffffu, s, o);
                if (lane >= o) s += y;
            }
            ws[lane] = s;
        }
        __syncthreads();
        int incl = x + (wid ? ws[wid - 1] : 0) + carry;
        if (i < NN) {
            int ex = incl - v;
            g_rowptr[i] = ex;
            g_cursor[i] = ex;
            if (i == NN - 1) g_rowptr[NN] = incl;
        }
        carry += ws[31];
        __syncthreads();
    }
}

__global__ void k_scatter(const int* __restrict__ ei) {
    int e = blockIdx.x * blockDim.x + threadIdx.x;
    if (e < EE) {
        int s = ei[e];
        int d = ei[EE + e];
        int pos = atomicAdd(&g_cursor[d], 1);
        g_col[pos] = s;
    }
}

// ---------------- GEMM1: h1 = x0 @ W1  (100000x128 @ 128x256) ----------------
__global__ void __launch_bounds__(256) k_gemm1(const float* __restrict__ x0,
                                               const float* __restrict__ W1) {
    __shared__ __align__(16) float As[16][128];  // transposed A tile
    __shared__ __align__(16) float Bs[16][128];
    int tid = threadIdx.x;
    int rowBase = blockIdx.y * 128;
    int colBase = blockIdx.x * 128;
    int ty = tid >> 4, tx = tid & 15;

    float acc[8][8];
    #pragma unroll
    for (int i = 0; i < 8; i++)
        #pragma unroll
        for (int j = 0; j < 8; j++) acc[i][j] = 0.f;

    int lr = tid >> 1, seg = tid & 1;

    for (int kb = 0; kb < 128; kb += 16) {
        // A: 128 rows x 16 k
        int row = rowBase + lr;
        float4 a0, a1;
        if (row < NN) {
            const float4* p = (const float4*)(x0 + (size_t)row * 128 + kb + seg * 8);
            a0 = p[0]; a1 = p[1];
        } else {
            a0 = make_float4(0, 0, 0, 0); a1 = a0;
        }
        As[seg * 8 + 0][lr] = a0.x; As[seg * 8 + 1][lr] = a0.y;
        As[seg * 8 + 2][lr] = a0.z; As[seg * 8 + 3][lr] = a0.w;
        As[seg * 8 + 4][lr] = a1.x; As[seg * 8 + 5][lr] = a1.y;
        As[seg * 8 + 6][lr] = a1.z; As[seg * 8 + 7][lr] = a1.w;
        // B: 16 k x 128 cols
        #pragma unroll
        for (int i = 0; i < 2; i++) {
            int f = tid + i * 256;           // float4 index within tile
            int kr = (f * 4) >> 7;
            int c  = (f * 4) & 127;
            float4 b = *(const float4*)(W1 + (size_t)(kb + kr) * 256 + colBase + c);
            *(float4*)&Bs[kr][c] = b;
        }
        __syncthreads();
        #pragma unroll
        for (int kk = 0; kk < 16; kk++) {
            float4 av0 = *(const float4*)&As[kk][ty * 8];
            float4 av1 = *(const float4*)&As[kk][ty * 8 + 4];
            float4 bv0 = *(const float4*)&Bs[kk][tx * 8];
            float4 bv1 = *(const float4*)&Bs[kk][tx * 8 + 4];
            float a[8] = {av0.x, av0.y, av0.z, av0.w, av1.x, av1.y, av1.z, av1.w};
            float b[8] = {bv0.x, bv0.y, bv0.z, bv0.w, bv1.x, bv1.y, bv1.z, bv1.w};
            #pragma unroll
            for (int i = 0; i < 8; i++)
                #pragma unroll
                for (int j = 0; j < 8; j++) acc[i][j] += a[i] * b[j];
        }
        __syncthreads();
    }
    #pragma unroll
    for (int i = 0; i < 8; i++) {
        int row = rowBase + ty * 8 + i;
        if (row < NN) {
            float4 v0 = make_float4(acc[i][0], acc[i][1], acc[i][2], acc[i][3]);
            float4 v1 = make_float4(acc[i][4], acc[i][5], acc[i][6], acc[i][7]);
            float* dst = g_h1 + (size_t)row * 256 + colBase + tx * 8;
            *(float4*)dst = v0;
            *(float4*)(dst + 4) = v1;
        }
    }
}

// ---------------- attention dots for layer 1 ----------------
__global__ void k_att1(const float* __restrict__ attS, const float* __restrict__ attD) {
    int warp = (blockIdx.x * blockDim.x + threadIdx.x) >> 5;
    int lane = threadIdx.x & 31;
    if (warp >= NN) return;
    const float* hrow = g_h1 + (size_t)warp * 256;
    #pragma unroll
    for (int h = 0; h < NH1; h++) {
        float v = hrow[h * 32 + lane];
        float ps = v * __ldg(&attS[h * 32 + lane]);
        float pd = v * __ldg(&attD[h * 32 + lane]);
        #pragma unroll
        for (int o = 16; o; o >>= 1) {
            ps += __shfl_xor_sync(0xffffffffu, ps, o);
            pd += __shfl_xor_sync(0xffffffffu, pd, o);
        }
        if (lane == 0) {
            g_as1[warp * 8 + h] = ps;
            g_ad1[warp * 8 + h] = pd;
        }
    }
}

// ---------------- GAT layer 1 aggregation (warp per dst node, online softmax) --------
__global__ void k_gat1(const float* __restrict__ b1) {
    int n = (blockIdx.x * blockDim.x + threadIdx.x) >> 5;
    int lane = threadIdx.x & 31;
    if (n >= NN) return;

    // lanes 0..7 own softmax stats for heads 0..7
    float adst = (lane < 8) ? g_ad1[n * 8 + lane] : 0.f;
    float m = -1e30f, den = 0.f;
    float acc[8];
    #pragma unroll
    for (int h = 0; h < 8; h++) acc[h] = 0.f;

    int e0 = g_rowptr[n], e1 = g_rowptr[n + 1];
    for (int e = e0 - 1; e < e1; e++) {          // e0-1 == implicit self loop
        int s = (e < e0) ? n : g_col[e];
        float asrc = (lane < 8) ? __ldg(&g_as1[s * 8 + lane]) : 0.f;
        float al = asrc + adst;
        al = al > 0.f ? al : NEGS * al;
        float nm = fmaxf(m, al);
        float p  = __expf(al - nm);
        float sc = __expf(m - nm);
        den = den * sc + p;
        m = nm;
        const float* hs = g_h1 + (size_t)s * 256;
        #pragma unroll
        for (int h = 0; h < 8; h++) {
            float ph  = __shfl_sync(0xffffffffu, p, h);
            float sch = __shfl_sync(0xffffffffu, sc, h);
            acc[h] = acc[h] * sch + ph * __ldg(&hs[h * 32 + lane]);
        }
    }
    float* orow = g_x2 + (size_t)n * 256;
    #pragma unroll
    for (int h = 0; h < 8; h++) {
        float dh = __shfl_sync(0xffffffffu, den, h);
        float r = acc[h] / fmaxf(dh, 1e-16f) + __ldg(&b1[h * 32 + lane]);
        orow[h * 32 + lane] = fmaxf(r, 0.f);     // relu for layer-2 input
    }
}

// ---------------- GEMM2: h2 = x2 @ W2 (256->32) + att2 dots fused ----------------
__global__ void __launch_bounds__(256) k_gemm2(const float* __restrict__ W2,
                                               const float* __restrict__ attS2,
                                               const float* __restrict__ attD2) {
    __shared__ float W2s[256 * 32];
    int tid = threadIdx.x;
    for (int i = tid; i < 256 * 32; i += 256) W2s[i] = W2[i];
    __syncthreads();
    int lane = tid & 31, wl = tid >> 5;
    int n = blockIdx.x * 8 + wl;                 // 12500*8 == 100000 exactly
    const float* xr = g_x2 + (size_t)n * 256;
    float acc = 0.f;
    #pragma unroll
    for (int c = 0; c < 8; c++) {
        float xv = xr[c * 32 + lane];
        #pragma unroll
        for (int j = 0; j < 32; j++) {
            float xb = __shfl_sync(0xffffffffu, xv, j);
            acc += xb * W2s[(c * 32 + j) * 32 + lane];
        }
    }
    g_h2[n * 32 + lane] = acc;
    float ps = acc * __ldg(&attS2[lane]);
    float pd = acc * __ldg(&attD2[lane]);
    #pragma unroll
    for (int o = 16; o; o >>= 1) {
        ps += __shfl_xor_sync(0xffffffffu, ps, o);
        pd += __shfl_xor_sync(0xffffffffu, pd, o);
    }
    if (lane == 0) { g_as2[n] = ps; g_ad2[n] = pd; }
}

// ---------------- GAT layer 2 aggregation (1 head) ----------------
__global__ void k_gat2(const float* __restrict__ b2) {
    int n = (blockIdx.x * blockDim.x + threadIdx.x) >> 5;
    int lane = threadIdx.x & 31;
    if (n >= NN) return;
    float adst = g_ad2[n];
    float m = -1e30f, den = 0.f, acc = 0.f;
    int e0 = g_rowptr[n], e1 = g_rowptr[n + 1];
    for (int e = e0 - 1; e < e1; e++) {
        int s = (e < e0) ? n : g_col[e];
        float asrc = __ldg(&g_as2[s]);
        float al = asrc + adst;
        al = al > 0.f ? al : NEGS * al;
        float nm = fmaxf(m, al);
        float p  = __expf(al - nm);
        float sc = __expf(m - nm);
        den = den * sc + p;
        m = nm;
        acc = acc * sc + p * __ldg(&g_h2[s * 32 + lane]);
    }
    g_o2[n * 32 + lane] = acc / fmaxf(den, 1e-16f) + __ldg(&b2[lane]);
}

// ---------------- final linear: out = o2 @ linW + linb (32->40) ----------------
__global__ void __launch_bounds__(640) k_final(const float* __restrict__ linW,
                                               const float* __restrict__ linb,
                                               float* __restrict__ out) {
    __shared__ float lw[32 * 40];
    __shared__ float rows[16][32];
    int tid = threadIdx.x;
    for (int i = tid; i < 32 * 40; i += 640) lw[i] = linW[i];
    int nb = blockIdx.x * 16;
    for (int i = tid; i < 512; i += 640) {
        int r = i >> 5, c = i & 31;
        int n = nb + r;
        rows[r][c] = (n < NN) ? g_o2[n * 32 + c] : 0.f;
    }
    __syncthreads();
    int o = tid % 40, r = tid / 40;
    int n = nb + r;
    if (n < NN) {
        float acc = __ldg(&linb[o]);
        #pragma unroll
        for (int k = 0; k < 32; k++) acc += rows[r][k] * lw[k * 40 + o];
        out[(size_t)n * 40 + o] = acc;
    }
}

// ---------------- launch ----------------
extern "C" void kernel_launch(void* const* d_in, const int* in_sizes, int n_in,
                              void* d_out, int out_size) {
    const float* x0    = (const float*)d_in[0];
    const float* W1    = (const float*)d_in[1];
    const float* attS1 = (const float*)d_in[2];
    const float* attD1 = (const float*)d_in[3];
    const float* b1    = (const float*)d_in[4];
    const float* W2    = (const float*)d_in[5];
    const float* attS2 = (const float*)d_in[6];
    const float* attD2 = (const float*)d_in[7];
    const float* b2    = (const float*)d_in[8];
    const float* linW  = (const float*)d_in[9];
    const float* linb  = (const float*)d_in[10];
    const int*   ei    = (const int*)d_in[11];   // int32 (JAX default, no x64)
    float* out = (float*)d_out;

    k_zero<<<(NN + 255) / 256, 256>>>();
    k_hist<<<(EE + 255) / 256, 256>>>(ei);
    k_scan<<<1, 1024>>>();
    k_scatter<<<(EE + 255) / 256, 256>>>(ei);
    k_gemm1<<<dim3(2, (NN + 127) / 128), 256>>>(x0, W1);
    k_att1<<<(NN + 7) / 8, 256>>>(attS1, attD1);
    k_gat1<<<(NN + 7) / 8, 256>>>(b1);
    k_gemm2<<<NN / 8, 256>>>(W2, attS2, attD2);
    k_gat2<<<(NN + 7) / 8, 256>>>(b2);
    k_final<<<(NN + 15) / 16, 640>>>(linW, linb, out);
}